// round 7
// baseline (speedup 1.0000x reference)
#include <cuda_runtime.h>

// out[t, 0, :] = inputs[t, :]
// out[t, l, :] = memory[l, :]  for l in [1, 64)
// T=2048, L=64, D=1024 (fp32). 512 MB pure-write kernel.
//
// R3 schedule with doubled stream length: grid (x=l fast, y=t-chunk),
// TT=32 t-rows per chunk (8 MB span). One l-row per block, register-held,
// single contiguous streaming-store stream of 32 STG.128 per thread.
// Resident wave spans ~18.5 chunks * 8MB = 148MB = 74 pages (< 128 TLB
// entries). Disentangles stream-length (good in R3 vs R4) from wave span
// (suspect in R5).

constexpr int T  = 2048;
constexpr int L  = 64;
constexpr int D  = 1024;
constexpr int D4 = D / 4;            // 256 float4 per row -> 256 threads
constexpr int ROW4 = L * D4;         // float4 per t
constexpr int TT = 32;               // t-values per block (8 MB chunk)
constexpr int CH = T / TT;           // 64 chunks along t

__global__ __launch_bounds__(256, 8)
void sliding_window_memory_kernel(const float4* __restrict__ inp,
                                  const float4* __restrict__ mem,
                                  float4* __restrict__ out) {
    const int l   = blockIdx.x;          // 0..63 (fast dim)
    const int t0  = blockIdx.y * TT;
    const int tid = threadIdx.x;         // float4 column 0..255

    if (l == 0) {
        // slot 0 depends on t: copy inputs[t0..t0+TT), streaming reads
        const float4* ip = inp + (size_t)t0 * D4 + tid;
        float4*       op = out + (size_t)t0 * ROW4 + tid;
        #pragma unroll
        for (int i = 0; i < TT; ++i) {
            __stcs(op, __ldcs(ip));
            ip += D4;
            op += ROW4;
        }
    } else {
        // slots 1..63: t-invariant row -> register-held, pure store stream
        const float4 v = __ldg(mem + (size_t)l * D4 + tid);
        float4* op = out + (size_t)t0 * ROW4 + (size_t)l * D4 + tid;
        #pragma unroll
        for (int i = 0; i < TT; ++i) {
            __stcs(op, v);
            op += ROW4;
        }
    }
}

extern "C" void kernel_launch(void* const* d_in, const int* in_sizes, int n_in,
                              void* d_out, int out_size) {
    const float4* inp = (const float4*)d_in[0];   // [T, D] fp32
    const float4* mem = (const float4*)d_in[1];   // [L, D] fp32
    float4* out = (float4*)d_out;                 // [T, L, D] fp32

    dim3 grid(L, CH);
    sliding_window_memory_kernel<<<grid, 256>>>(inp, mem, out);
}

// round 8
// speedup vs baseline: 1.0680x; 1.0680x over previous
#include <cuda_runtime.h>

// out[t, 0, :] = inputs[t, :]
// out[t, l, :] = memory[l, :]  for l in [1, 64)
// T=2048, L=64, D=1024 (fp32). 512 MB pure-write kernel.
//
// R3 schedule (best: 76.8us) + occupancy cap. Grid (x=l fast, y=t-chunk),
// TT=16, one l-row per block, register-held, 16 streaming STG.128 per thread.
// 40KB dynamic smem per block (unused) caps residency at ~5 blocks/SM:
//   resident ~740 blocks -> concurrent wave spans ~46MB (vs 74MB at occ 8),
//   tail idle ~4.5% (vs 7%). Only the wave address span changes vs R3.

constexpr int T  = 2048;
constexpr int L  = 64;
constexpr int D  = 1024;
constexpr int D4 = D / 4;            // 256 float4 per row -> 256 threads
constexpr int ROW4 = L * D4;         // float4 per t
constexpr int TT = 16;               // t-values per block (4 MB chunk)
constexpr int CH = T / TT;           // 128 chunks along t
constexpr int SMEM_CAP = 40 * 1024;  // occupancy limiter (unused scratch)

__global__ __launch_bounds__(256)
void sliding_window_memory_kernel(const float4* __restrict__ inp,
                                  const float4* __restrict__ mem,
                                  float4* __restrict__ out) {
    extern __shared__ char occupancy_pad[];   // never touched
    (void)occupancy_pad;

    const int l   = blockIdx.x;          // 0..63 (fast dim)
    const int t0  = blockIdx.y * TT;
    const int tid = threadIdx.x;         // float4 column 0..255

    if (l == 0) {
        // slot 0 depends on t: copy inputs[t0..t0+TT), streaming reads
        const float4* ip = inp + (size_t)t0 * D4 + tid;
        float4*       op = out + (size_t)t0 * ROW4 + tid;
        #pragma unroll
        for (int i = 0; i < TT; ++i) {
            __stcs(op, __ldcs(ip));
            ip += D4;
            op += ROW4;
        }
    } else {
        // slots 1..63: t-invariant row -> register-held, pure store stream
        const float4 v = __ldg(mem + (size_t)l * D4 + tid);
        float4* op = out + (size_t)t0 * ROW4 + (size_t)l * D4 + tid;
        #pragma unroll
        for (int i = 0; i < TT; ++i) {
            __stcs(op, v);
            op += ROW4;
        }
    }
}

extern "C" void kernel_launch(void* const* d_in, const int* in_sizes, int n_in,
                              void* d_out, int out_size) {
    const float4* inp = (const float4*)d_in[0];   // [T, D] fp32
    const float4* mem = (const float4*)d_in[1];   // [L, D] fp32
    float4* out = (float4*)d_out;                 // [T, L, D] fp32

    dim3 grid(L, CH);
    sliding_window_memory_kernel<<<grid, 256, SMEM_CAP>>>(inp, mem, out);
}